// round 4
// baseline (speedup 1.0000x reference)
#include <cuda_runtime.h>

// QLSTM: B=512, T=1024, IN=1, H=64.
// Persistent blocks: 128 blocks x 128 threads, 4 batches per block.
// Thread (u, bs): u in [0,64) hidden unit, bs in {0,1} selects batch pair
// {2*bs, 2*bs+1}. Each thread computes gates i,f,g,o for its unit for 2
// batches (8 fp32 accumulators), owns c in registers, h shared via SMEM.

#define TPB 128
#define GB  4        // batches per block
#define TSTEPS 1024

struct Smem {
  float4 Wg[64][65];     // gate-packed W_hh: Wg[u][k] = {Wi,Wf,Wg,Wo}[u,k], pad 65 for banks
  float4 bias4[64];      // b_ih + b_hh, gate-packed
  float4 wih4[64];       // W_ih (IN=1), gate-packed
  float  xs[GB][TSTEPS]; // input slice for this block's batches
  float  hsh[GB][64];    // hidden state
  float  wlin[64];       // final linear weights
};

__device__ __forceinline__ float sigf(float v) {
  return __fdividef(1.0f, 1.0f + __expf(-v));
}
__device__ __forceinline__ float tanhf_fast(float v) {
  // 1 - 2/(e^{2v}+1): exact saturation at +/-inf of expf, ~ulp-accurate mid-range
  return 1.0f - __fdividef(2.0f, __expf(2.0f * v) + 1.0f);
}

__device__ __forceinline__ void fma4(float4& acc, const float4& wv, float hv) {
  acc.x = fmaf(wv.x, hv, acc.x);
  acc.y = fmaf(wv.y, hv, acc.y);
  acc.z = fmaf(wv.z, hv, acc.z);
  acc.w = fmaf(wv.w, hv, acc.w);
}

extern __shared__ char smem_raw[];

__global__ void __launch_bounds__(TPB, 1) qlstm_kernel(
    const float* __restrict__ x,      // [B, T, 1]
    const float* __restrict__ W_ih,   // [256, 1]
    const float* __restrict__ W_hh,   // [256, 64]
    const float* __restrict__ b_ih,   // [256]
    const float* __restrict__ b_hh,   // [256]
    const float* __restrict__ W_lin,  // [1, 64]
    const float* __restrict__ b_lin,  // [1]
    float* __restrict__ out)          // [B]
{
  Smem& s = *reinterpret_cast<Smem*>(smem_raw);
  const int t  = threadIdx.x;
  const int u  = t & 63;
  const int bs = t >> 6;          // 0 or 1
  const int b0 = 2 * bs;
  const int b1 = b0 + 1;
  const int batch0 = blockIdx.x * GB;

  // ---- one-time staging ----
  for (int idx = t; idx < 64 * 64; idx += TPB) {
    int uu = idx >> 6, kk = idx & 63;
    float4 w;
    w.x = W_hh[(uu)       * 64 + kk];   // i
    w.y = W_hh[(64 + uu)  * 64 + kk];   // f
    w.z = W_hh[(128 + uu) * 64 + kk];   // g
    w.w = W_hh[(192 + uu) * 64 + kk];   // o
    s.Wg[uu][kk] = w;
  }
  if (t < 64) {
    float4 bb;
    bb.x = b_ih[t]       + b_hh[t];
    bb.y = b_ih[64 + t]  + b_hh[64 + t];
    bb.z = b_ih[128 + t] + b_hh[128 + t];
    bb.w = b_ih[192 + t] + b_hh[192 + t];
    s.bias4[t] = bb;
    float4 wi;
    wi.x = W_ih[t];
    wi.y = W_ih[64 + t];
    wi.z = W_ih[128 + t];
    wi.w = W_ih[192 + t];
    s.wih4[t] = wi;
    s.wlin[t] = W_lin[t];
  }
  for (int idx = t; idx < GB * TSTEPS; idx += TPB) {
    int bb = idx >> 10, tt = idx & (TSTEPS - 1);
    s.xs[bb][tt] = x[(batch0 + bb) * TSTEPS + tt];
  }
  for (int idx = t; idx < GB * 64; idx += TPB)
    (&s.hsh[0][0])[idx] = 0.0f;
  __syncthreads();

  const float4 bias = s.bias4[u];
  const float4 wih  = s.wih4[u];
  const float4* __restrict__ Wrow = s.Wg[u];
  float cA = 0.0f, cB = 0.0f;

  for (int step = 0; step < TSTEPS; step++) {
    const float xa = s.xs[b0][step];
    const float xb = s.xs[b1][step];
    float4 a0, a1;
    a0.x = fmaf(xa, wih.x, bias.x);
    a0.y = fmaf(xa, wih.y, bias.y);
    a0.z = fmaf(xa, wih.z, bias.z);
    a0.w = fmaf(xa, wih.w, bias.w);
    a1.x = fmaf(xb, wih.x, bias.x);
    a1.y = fmaf(xb, wih.y, bias.y);
    a1.z = fmaf(xb, wih.z, bias.z);
    a1.w = fmaf(xb, wih.w, bias.w);

    const float4* __restrict__ h0p = reinterpret_cast<const float4*>(s.hsh[b0]);
    const float4* __restrict__ h1p = reinterpret_cast<const float4*>(s.hsh[b1]);
#pragma unroll
    for (int k4 = 0; k4 < 16; k4++) {
      float4 h0 = h0p[k4];          // broadcast within warp (all lanes same bs)
      float4 h1 = h1p[k4];
      float4 w0 = Wrow[4 * k4 + 0]; // conflict-free LDS.128 (65-pad)
      float4 w1 = Wrow[4 * k4 + 1];
      float4 w2 = Wrow[4 * k4 + 2];
      float4 w3 = Wrow[4 * k4 + 3];
      fma4(a0, w0, h0.x); fma4(a1, w0, h1.x);
      fma4(a0, w1, h0.y); fma4(a1, w1, h1.y);
      fma4(a0, w2, h0.z); fma4(a1, w2, h1.z);
      fma4(a0, w3, h0.w); fma4(a1, w3, h1.w);
    }

    // activations + cell update (no shared access -> before the read barrier)
    const float i0 = sigf(a0.x), f0 = sigf(a0.y), g0 = tanhf_fast(a0.z), o0 = sigf(a0.w);
    const float i1 = sigf(a1.x), f1 = sigf(a1.y), g1 = tanhf_fast(a1.z), o1 = sigf(a1.w);
    cA = fmaf(f0, cA, i0 * g0);
    cB = fmaf(f1, cB, i1 * g1);
    const float hn0 = o0 * tanhf_fast(cA);
    const float hn1 = o1 * tanhf_fast(cB);

    __syncthreads();               // all hsh reads of this step done
    s.hsh[b0][u] = hn0;
    s.hsh[b1][u] = hn1;
    __syncthreads();               // writes visible for next step
  }

  // final linear: out[b] = h_final[b] . W_lin + b_lin
  if (t < GB) {
    float sum = b_lin[0];
#pragma unroll
    for (int k = 0; k < 64; k++)
      sum = fmaf(s.hsh[t][k], s.wlin[k], sum);
    out[batch0 + t] = sum;
  }
}

extern "C" void kernel_launch(void* const* d_in, const int* in_sizes, int n_in,
                              void* d_out, int out_size) {
  const float* x     = (const float*)d_in[0];
  const float* W_ih  = (const float*)d_in[1];
  const float* W_hh  = (const float*)d_in[2];
  const float* b_ih  = (const float*)d_in[3];
  const float* b_hh  = (const float*)d_in[4];
  const float* W_lin = (const float*)d_in[5];
  const float* b_lin = (const float*)d_in[6];
  float* out = (float*)d_out;

  const int B = out_size;  // 512
  const int nblocks = B / GB;

  cudaFuncSetAttribute(qlstm_kernel,
                       cudaFuncAttributeMaxDynamicSharedMemorySize,
                       (int)sizeof(Smem));
  qlstm_kernel<<<nblocks, TPB, sizeof(Smem)>>>(x, W_ih, W_hh, b_ih, b_hh,
                                               W_lin, b_lin, out);
}